// round 15
// baseline (speedup 1.0000x reference)
#include <cuda_runtime.h>
#include <cstdint>
#include <math.h>

// ============================================================================
// libdevice-matching transcendentals
// ============================================================================
#if defined(__USE_FAST_MATH__)
__device__ __forceinline__ float xlogf(float x){ return (float)log((double)x); }
__device__ __forceinline__ float xlog1pf(float x){ return (float)log1p((double)x); }
__device__ __forceinline__ float xexpf(float x){ return (float)exp((double)x); }
#else
__device__ __forceinline__ float xlogf(float x){ return logf(x); }
__device__ __forceinline__ float xlog1pf(float x){ return log1pf(x); }
__device__ __forceinline__ float xexpf(float x){ return expf(x); }
#endif

// ============================================================================
// Threefry-2x32 (exact JAX partitionable replication)
// ============================================================================
#define TF_C 0x1BD11BDAu

struct U2 { uint32_t a, b; };

__device__ __forceinline__ uint32_t rotl32(uint32_t x, int r){
    return __funnelshift_l(x, x, r);
}

__device__ __forceinline__ U2 threefry(uint32_t k0, uint32_t k1, uint32_t x0, uint32_t x1){
    uint32_t k2 = k0 ^ k1 ^ TF_C;
    x0 += k0; x1 += k1;
#define TFR(r) { x0 += x1; x1 = rotl32(x1, (r)); x1 ^= x0; }
    TFR(13) TFR(15) TFR(26) TFR(6)
    x0 += k1; x1 += k2 + 1u;
    TFR(17) TFR(29) TFR(16) TFR(24)
    x0 += k2; x1 += k0 + 2u;
    TFR(13) TFR(15) TFR(26) TFR(6)
    x0 += k0; x1 += k1 + 3u;
    TFR(17) TFR(29) TFR(16) TFR(24)
    x0 += k1; x1 += k2 + 4u;
    TFR(13) TFR(15) TFR(26) TFR(6)
    x0 += k2; x1 += k0 + 5u;
#undef TFR
    U2 r; r.a = x0; r.b = x1; return r;
}

__device__ __forceinline__ uint32_t tf_bits(uint32_t k0, uint32_t k1, uint32_t idx){
    U2 o = threefry(k0, k1, 0u, idx);
    return o.a ^ o.b;
}

__device__ __forceinline__ float u01(uint32_t bits){
    return __uint_as_float((bits >> 9) | 0x3f800000u) - 1.0f;
}

// XLA ErfInv32 (Giles polynomial)
__device__ __forceinline__ float erfinv_xla(float x){
    float w = -xlog1pf(-x * x);
    float p;
    if (w < 5.0f){
        w = w - 2.5f;
        p = 2.81022636e-08f;
        p = fmaf(p, w, 3.43273939e-07f);
        p = fmaf(p, w, -3.5233877e-06f);
        p = fmaf(p, w, -4.39150654e-06f);
        p = fmaf(p, w, 0.00021858087f);
        p = fmaf(p, w, -0.00125372503f);
        p = fmaf(p, w, -0.00417768164f);
        p = fmaf(p, w, 0.246640727f);
        p = fmaf(p, w, 1.50140941f);
    } else {
        w = sqrtf(w) - 3.0f;
        p = -0.000200214257f;
        p = fmaf(p, w, 0.000100950558f);
        p = fmaf(p, w, 0.00134934322f);
        p = fmaf(p, w, -0.00367342844f);
        p = fmaf(p, w, 0.00573950773f);
        p = fmaf(p, w, -0.0076224613f);
        p = fmaf(p, w, 0.00943887047f);
        p = fmaf(p, w, 1.00167406f);
        p = fmaf(p, w, 2.83297682f);
    }
    return p * x;
}

// ============================================================================
// tf32 helpers
// ============================================================================
__device__ __forceinline__ uint32_t f2tf32(float x){
    uint32_t r;
    asm("cvt.rna.tf32.f32 %0, %1;" : "=r"(r) : "f"(x));
    return r;
}

__device__ __forceinline__ void mma_tf32(
    float& c0, float& c1, float& c2, float& c3,
    uint32_t a0, uint32_t a1, uint32_t a2, uint32_t a3,
    uint32_t b0, uint32_t b1)
{
    asm volatile(
        "mma.sync.aligned.m16n8k8.row.col.f32.tf32.tf32.f32 "
        "{%0,%1,%2,%3},{%4,%5,%6,%7},{%8,%9},{%0,%1,%2,%3};"
        : "+f"(c0), "+f"(c1), "+f"(c2), "+f"(c3)
        : "r"(a0), "r"(a1), "r"(a2), "r"(a3), "r"(b0), "r"(b1));
}

// D fragment (m16n8) -> A fragment (m16k8) via intra-quad shuffles (validated)
__device__ __forceinline__ void dfrag_to_afrag(
    uint32_t x0, uint32_t x1, uint32_t x2, uint32_t x3,
    uint32_t& a0, uint32_t& a1, uint32_t& a2, uint32_t& a3, int lane)
{
    int t = lane & 3;
    int srcA = (lane & ~3) | (t >> 1);
    int srcB = srcA + 2;
    uint32_t s0 = __shfl_sync(0xffffffffu, x0, srcA);
    uint32_t s1 = __shfl_sync(0xffffffffu, x1, srcA);
    uint32_t s2 = __shfl_sync(0xffffffffu, x0, srcB);
    uint32_t s3 = __shfl_sync(0xffffffffu, x1, srcB);
    a0 = (t & 1) ? s1 : s0;
    a2 = (t & 1) ? s3 : s2;
    uint32_t u0 = __shfl_sync(0xffffffffu, x2, srcA);
    uint32_t u1 = __shfl_sync(0xffffffffu, x3, srcA);
    uint32_t u2 = __shfl_sync(0xffffffffu, x2, srcB);
    uint32_t u3 = __shfl_sync(0xffffffffu, x3, srcB);
    a1 = (t & 1) ? u1 : u0;
    a3 = (t & 1) ? u3 : u2;
}

// ============================================================================
// Device scratch
// ============================================================================
__device__ uint2 g_k1[64];
__device__ uint2 g_k2[64];
__device__ uint2 g_kv;
__device__ float g_norm[4194304];    // [B][32] raw normals (31 used)
__device__ uint32_t g_zf[4194304];   // z in tf32 A-fragment layout
__device__ uint32_t g_w1f[16384];    // W1 B-fragments (tf32 bits)
__device__ uint32_t g_w2f[16384];    // W2 B-fragments
__device__ uint32_t g_w3f[256];      // W3 B-fragments (col 7 zero)
__device__ uint2 g_wmuh[8192];       // Wmu B-fragments, hi part

// ============================================================================
// Kernel 1: RNG keys (partitionable semantics)
// ============================================================================
__global__ void k_setup(const int* __restrict__ seedp){
    int i = threadIdx.x;
    uint32_t s = (uint32_t)seedp[0];
    if (i < 50){
        U2 fk = threefry(0u, s, 0u, (uint32_t)i);
        U2 kw = threefry(fk.a, fk.b, 0u, 0u);
        U2 kr = threefry(fk.a, fk.b, 0u, 1u);
        g_k1[i] = make_uint2(kw.a, kw.b);
        g_k2[i] = make_uint2(kr.a, kr.b);
    } else if (i == 50){
        U2 kv = threefry(0u, s, 0u, 10000u);
        g_kv = make_uint2(kv.a, kv.b);
    }
}

// ============================================================================
// Kernel 1b: pack weights into tf32 B-fragments (W1/W2/W3 + Wmu hi)
// ============================================================================
__global__ void k_packw(const float* __restrict__ W1,
                        const float* __restrict__ W2,
                        const float* __restrict__ W3,
                        const float* __restrict__ Wmu){
    int j = blockIdx.x * 256 + threadIdx.x;
    if (j < 16384){
        int p = j & 1, lane = (j >> 1) & 31, kc = (j >> 6) & 3, nt = j >> 8;
        int g = lane >> 2, t = lane & 3;
        g_w1f[j] = f2tf32(W1[(nt * 8 + g) * 32 + kc * 8 + t + 4 * p]);
    } else if (j < 32768){
        int j2 = j - 16384;
        int p = j2 & 1, lane = (j2 >> 1) & 31, kc2 = (j2 >> 6) & 63, nt2 = j2 >> 12;
        int g = lane >> 2, t = lane & 3;
        g_w2f[j2] = f2tf32(W2[(nt2 * 8 + g) * 512 + kc2 * 8 + t + 4 * p]);
    } else if (j < 33024){
        int j3 = j - 32768;
        int p = j3 & 1, lane = (j3 >> 1) & 31, kc = (j3 >> 6) & 3;
        int g = lane >> 2, t = lane & 3;
        g_w3f[j3] = (g < 7) ? f2tf32(W3[g * 32 + kc * 8 + t + 4 * p]) : 0u;
    } else if (j < 41216){
        int jm = j - 33024;                 // 0..8191
        int lane = jm & 31, nt = (jm >> 5) & 3, kc = jm >> 7;   // kc 0..63
        int g = lane >> 2, t = lane & 3;
        float x0 = Wmu[(nt * 8 + g) * 512 + kc * 8 + t];
        float x1 = Wmu[(nt * 8 + g) * 512 + kc * 8 + t + 4];
        g_wmuh[jm] = make_uint2(f2tf32(x0), f2tf32(x1));
    }
}

// ============================================================================
// Kernel 2: normals — RNG index e = b*31+c, stored at stride 32 (proven)
// ============================================================================
__global__ void __launch_bounds__(256) k_normals(int n){
    int e = blockIdx.x * 256 + threadIdx.x;
    if (e >= n) return;
    uint2 kv = g_kv;
    uint32_t bits = tf_bits(kv.x, kv.y, (uint32_t)e);
    float f = u01(bits);
    const float lo = -0.99999994f;
    float u = fmaxf(lo, __fadd_rn(__fmul_rn(f, 2.0f), lo));
    int b = e / 31, c = e - b * 31;
    g_norm[b * 32 + c] = __fmul_rn(1.41421356f, erfinv_xla(u));
}

// ============================================================================
// Kernel 3: FUSED tensor-core encode GEMM + Wood + Householder + frag store.
// R15: register double-buffered h stream (prefetch chunk c+1 during compute c).
// mu via 2-term split tf32; kappa exact fp32 chain. 128 rows/CTA, 2 CTAs/SM.
// ============================================================================
__global__ void __launch_bounds__(256, 2) k_gemmTCF(
    const float* __restrict__ h,
    const float* __restrict__ bmu,
    const float* __restrict__ Wk, const float* __restrict__ bk,
    float* __restrict__ outp, int B)
{
    extern __shared__ char smraw[];
    uint2* wh  = (uint2*)smraw;            // 8192 uint2 (64KB) Wmu hi frags
    float* hs  = (float*)(wh + 8192);      // [128][68] (34.8KB); reused as muS
    float* wks = hs + 128 * 68;            // [512]
    uint2* sk1 = (uint2*)(wks + 512);      // [50]
    uint2* sk2 = sk1 + 50;                 // [50]

    const int tid  = threadIdx.x;
    const int warp = tid >> 5;
    const int lane = tid & 31;
    const int g = lane >> 2;
    const int t = lane & 3;
    const int row0 = blockIdx.x * 128;

    // stage B fragments + Wk + RNG keys
    {
        const uint4* sh = (const uint4*)g_wmuh;
        uint4* dh = (uint4*)wh;
        for (int i = tid; i < 4096; i += 256) dh[i] = sh[i];
        for (int i = tid; i < 512; i += 256) wks[i] = Wk[i];
        if (tid < 50)       sk1[tid] = g_k1[tid];
        else if (tid < 100) sk2[tid - 50] = g_k2[tid - 50];
    }

    float acc[4][4];
#pragma unroll
    for (int nt = 0; nt < 4; nt++)
#pragma unroll
        for (int i = 0; i < 4; i++) acc[nt][i] = 0.0f;

    float ka = 0.0f;
    const float4* h4 = (const float4*)h;

    // per-thread load coordinates (fixed across chunks)
    const int lr = tid >> 1;               // 0..127 row (2 threads per row)
    const int lq = (tid & 1) * 8;          // col offset 0 or 8
    const size_t hbase = (size_t)(row0 + lr) * 128 + lq;

    // prefetch chunk 0
    float4 pre[8];
#pragma unroll
    for (int q = 0; q < 8; q++) pre[q] = h4[hbase + q];

    for (int c = 0; c < 8; c++){                  // 8 chunks of 64 k
        __syncthreads();
        // commit prefetched chunk to smem
#pragma unroll
        for (int q = 0; q < 8; q++)
            *(float4*)&hs[lr * 68 + (lq + q) * 4] = pre[q];
        __syncthreads();

        // prefetch next chunk (LDGs overlap with the compute below)
        if (c < 7){
            const size_t nb = hbase + (size_t)(c + 1) * 16;
#pragma unroll
            for (int q = 0; q < 8; q++) pre[q] = h4[nb + q];
        }

        // --- mma over 8 k-groups (1 tile/warp = 16 rows) ---
#pragma unroll
        for (int kc = 0; kc < 8; kc++){
            const int rb = (warp * 16 + g) * 68 + kc * 8 + t;
            float a0f = hs[rb];
            float a1f = hs[rb + 8 * 68];
            float a2f = hs[rb + 4];
            float a3f = hs[rb + 8 * 68 + 4];
            uint32_t ah0 = f2tf32(a0f), ah1 = f2tf32(a1f);
            uint32_t ah2 = f2tf32(a2f), ah3 = f2tf32(a3f);
            uint32_t al0 = f2tf32(a0f - __uint_as_float(ah0));
            uint32_t al1 = f2tf32(a1f - __uint_as_float(ah1));
            uint32_t al2 = f2tf32(a2f - __uint_as_float(ah2));
            uint32_t al3 = f2tf32(a3f - __uint_as_float(ah3));
            const int kcg = c * 8 + kc;
#pragma unroll
            for (int nt = 0; nt < 4; nt++){
                uint2 bh = wh[(kcg * 4 + nt) * 32 + lane];
                mma_tf32(acc[nt][0], acc[nt][1], acc[nt][2], acc[nt][3],
                         al0, al1, al2, al3, bh.x, bh.y);
                mma_tf32(acc[nt][0], acc[nt][1], acc[nt][2], acc[nt][3],
                         ah0, ah1, ah2, ah3, bh.x, bh.y);
            }
        }

        // --- kappa: exact fp32 chain, k ascending, rows 0..127 (tid<128) ---
        if (tid < 128){
            const float4* hr = (const float4*)&hs[tid * 68];
#pragma unroll
            for (int q = 0; q < 16; q++){
                float4 v = hr[q];
                const int kb = c * 64 + q * 4;
                ka = fmaf(v.x, wks[kb],     ka);
                ka = fmaf(v.y, wks[kb + 1], ka);
                ka = fmaf(v.z, wks[kb + 2], ka);
                ka = fmaf(v.w, wks[kb + 3], ka);
            }
        }
    }

    // --- epilogue: bias + l2norm; write mu to gmem AND smem (muS) ---
    __syncthreads();                       // hs free -> reuse as muS [128][33]
    float* muS = hs;
    {
        float ssA = 0.0f, ssB = 0.0f;
#pragma unroll
        for (int nt = 0; nt < 4; nt++){
            float b0 = bmu[nt * 8 + 2 * t];
            float b1 = bmu[nt * 8 + 2 * t + 1];
            acc[nt][0] += b0; acc[nt][1] += b1;
            acc[nt][2] += b0; acc[nt][3] += b1;
            ssA = fmaf(acc[nt][0], acc[nt][0], ssA);
            ssA = fmaf(acc[nt][1], acc[nt][1], ssA);
            ssB = fmaf(acc[nt][2], acc[nt][2], ssB);
            ssB = fmaf(acc[nt][3], acc[nt][3], ssB);
        }
        ssA += __shfl_xor_sync(0xffffffffu, ssA, 1);
        ssA += __shfl_xor_sync(0xffffffffu, ssA, 2);
        ssB += __shfl_xor_sync(0xffffffffu, ssB, 1);
        ssB += __shfl_xor_sync(0xffffffffu, ssB, 2);
        float denA = fmaxf(sqrtf(ssA), 1e-12f);
        float denB = fmaxf(sqrtf(ssB), 1e-12f);

        const int lA = warp * 16 + g;      // local rows
        const int lB = lA + 8;
        const int rA = row0 + lA;
        const int rB = row0 + lB;
        const size_t muA = (size_t)B * 7 + (size_t)rA * 32;
        const size_t muB = (size_t)B * 7 + (size_t)rB * 32;
#pragma unroll
        for (int nt = 0; nt < 4; nt++){
            float mA0 = acc[nt][0] / denA;
            float mA1 = acc[nt][1] / denA;
            float mB0 = acc[nt][2] / denB;
            float mB1 = acc[nt][3] / denB;
            outp[muA + nt * 8 + 2 * t]     = mA0;
            outp[muA + nt * 8 + 2 * t + 1] = mA1;
            outp[muB + nt * 8 + 2 * t]     = mB0;
            outp[muB + nt * 8 + 2 * t + 1] = mB1;
            muS[lA * 33 + nt * 8 + 2 * t]     = mA0;
            muS[lA * 33 + nt * 8 + 2 * t + 1] = mA1;
            muS[lB * 33 + nt * 8 + 2 * t]     = mB0;
            muS[lB * 33 + nt * 8 + 2 * t + 1] = mB1;
        }
    }

    // --- kappa epilogue (exact fp32 ops as all passing rounds) ---
    float kappa = 0.0f;
    if (tid < 128){
        float x = __fadd_rn(ka, bk[0]);
        float sp = __fadd_rn(fmaxf(x, 0.0f), xlog1pf(xexpf(-fabsf(x))));
        kappa = __fadd_rn(sp, 1.0f);
        outp[(size_t)B * 39 + (row0 + tid)] = kappa;
    }
    __syncthreads();

    // --- fused z-prep: Wood + z_tilde + Householder + frag store (tid<128) ---
    if (tid < 128){
        const int row = row0 + tid;
        const uint32_t ub = (uint32_t)row;

        // Wood's rejection (exact f32 op order)
        float w = 0.0f;
        bool done = false;
        for (int i = 0; i < 50; i++){
            if (__all_sync(0xffffffffu, done)) break;
            if (!done){
                uint2 K1 = sk1[i];
                float u1 = u01(tf_bits(K1.x, K1.y, ub));
                float wc = __fsub_rn(__fmul_rn(2.0f, u1), 1.0f);
                float omw = fmaxf(__fsub_rn(1.0f, __fmul_rn(wc, wc)), 1e-38f);
                float logp = __fadd_rn(__fmul_rn(kappa, wc), __fmul_rn(14.5f, xlogf(omw)));
                uint2 K2 = sk2[i];
                float u2 = u01(tf_bits(K2.x, K2.y, ub));
                float logr = xlogf(__fadd_rn(u2, 1e-38f));
                if (__fadd_rn(logr, kappa) <= logp){ w = wc; done = true; }
            }
        }
        w = fminf(fmaxf(w, -1.0f), 1.0f);

        // z_tilde
        float z[32];
        {
            const float4* nv = (const float4*)&g_norm[(size_t)row * 32];
#pragma unroll
            for (int q = 0; q < 8; q++){
                float4 v = nv[q];
                z[q * 4 + 0] = v.x; z[q * 4 + 1] = v.y;
                z[q * 4 + 2] = v.z; z[q * 4 + 3] = v.w;
            }
            z[31] = 0.0f;
            float ssn = 0.0f;
#pragma unroll
            for (int c = 0; c < 31; c++) ssn = fmaf(z[c], z[c], ssn);
            float den = fmaxf(sqrtf(ssn), 1e-12f);
            float st  = sqrtf(fmaxf(__fsub_rn(1.0f, __fmul_rn(w, w)), 1e-38f));
            float sc  = st / den;
#pragma unroll
            for (int c = 0; c < 31; c++) z[c] *= sc;
            z[31] = w;
        }

        // Householder (mu from smem)
        {
            const float* mrow = &muS[tid * 33];
            float uh[32];
            float ssu = 0.0f;
#pragma unroll
            for (int q = 0; q < 8; q++){
                float m0 = mrow[q * 4 + 0];
                float m1 = mrow[q * 4 + 1];
                float m2 = mrow[q * 4 + 2];
                float m3 = mrow[q * 4 + 3];
                float t0 = ((q * 4 + 0) == 31 ? 1.0f : 0.0f) - m0;
                float t1 = ((q * 4 + 1) == 31 ? 1.0f : 0.0f) - m1;
                float t2 = ((q * 4 + 2) == 31 ? 1.0f : 0.0f) - m2;
                float t3 = ((q * 4 + 3) == 31 ? 1.0f : 0.0f) - m3;
                uh[q * 4 + 0] = t0; uh[q * 4 + 1] = t1;
                uh[q * 4 + 2] = t2; uh[q * 4 + 3] = t3;
                ssu = fmaf(t0, t0, ssu); ssu = fmaf(t1, t1, ssu);
                ssu = fmaf(t2, t2, ssu); ssu = fmaf(t3, t3, ssu);
            }
            float inv = 1.0f / fmaxf(sqrtf(ssu), 1e-12f);
            float dot = 0.0f;
#pragma unroll
            for (int j = 0; j < 32; j++){
                uh[j] *= inv;
                dot = fmaf(z[j], uh[j], dot);
            }
            float d2 = 2.0f * dot;
#pragma unroll
            for (int j = 0; j < 32; j++) z[j] = fmaf(-d2, uh[j], z[j]);
        }

        // frag store (validated layout)
        {
            const int tIdx = row >> 4;
            const int lrr  = row & 15;
            const int gg   = lrr & 7;
            const int hhp  = (lrr >> 3) & 1;
#pragma unroll
            for (int kc = 0; kc < 4; kc++){
#pragma unroll
                for (int tt = 0; tt < 4; tt++){
                    size_t base = ((size_t)(tIdx * 4 + kc) * 32 + (gg * 4 + tt)) * 4;
                    g_zf[base + hhp]     = f2tf32(z[kc * 8 + tt]);
                    g_zf[base + 2 + hhp] = f2tf32(z[kc * 8 + tt + 4]);
                }
            }
        }
    }
}

// ============================================================================
// Kernel 4: tensor-core MLP, 2 tiles per warp (proven R12-R14)
// ============================================================================
__global__ void __launch_bounds__(256) k_mlp_tc(
    const float* __restrict__ b1, const float* __restrict__ b2,
    const float* __restrict__ b3,
    float* __restrict__ outp, int B, int nTiles)
{
    extern __shared__ char smraw[];
    uint32_t* w1s = (uint32_t*)smraw;        // 16384
    uint32_t* w2s = w1s + 16384;             // 16384
    uint32_t* w3s = w2s + 16384;             // 256
    float* b1s = (float*)(w3s + 256);        // 512
    float* b2s = b1s + 512;                  // 32
    float* b3s = b2s + 32;                   // 8

    const int tid = threadIdx.x;
    {
        const uint4* s1 = (const uint4*)g_w1f;
        const uint4* s2 = (const uint4*)g_w2f;
        uint4* d1 = (uint4*)w1s;
        uint4* d2 = (uint4*)w2s;
        for (int i = tid; i < 4096; i += 256){ d1[i] = s1[i]; d2[i] = s2[i]; }
        if (tid < 64) ((uint4*)w3s)[tid] = ((const uint4*)g_w3f)[tid];
        for (int i = tid; i < 512; i += 256) b1s[i] = b1[i];
        if (tid < 32) b2s[tid] = b2[tid];
        if (tid < 8)  b3s[tid] = (tid < 7) ? b3[tid] : 0.0f;
    }
    __syncthreads();

    const int warp = tid >> 5;
    const int lane = tid & 31;
    const int g = lane >> 2;
    const int t = lane & 3;
    const int nPairs = nTiles >> 1;

    for (int tp = blockIdx.x * 8 + warp; tp < nPairs; tp += 148 * 8){
        const int t0 = 2 * tp, t1 = t0 + 1;

        uint32_t azA[4][4], azB[4][4];
        {
            const uint4* zpA = (const uint4*)&g_zf[(size_t)t0 * 512];
            const uint4* zpB = (const uint4*)&g_zf[(size_t)t1 * 512];
#pragma unroll
            for (int kc = 0; kc < 4; kc++){
                uint4 vA = zpA[kc * 32 + lane];
                azA[kc][0] = vA.x; azA[kc][1] = vA.y; azA[kc][2] = vA.z; azA[kc][3] = vA.w;
                uint4 vB = zpB[kc * 32 + lane];
                azB[kc][0] = vB.x; azB[kc][1] = vB.y; azB[kc][2] = vB.z; azB[kc][3] = vB.w;
            }
        }

        float a2A[4][4], a2B[4][4];
#pragma unroll
        for (int n2 = 0; n2 < 4; n2++){
            float bb0 = b2s[n2 * 8 + 2 * t];
            float bb1 = b2s[n2 * 8 + 2 * t + 1];
            a2A[n2][0] = bb0; a2A[n2][1] = bb1; a2A[n2][2] = bb0; a2A[n2][3] = bb1;
            a2B[n2][0] = bb0; a2B[n2][1] = bb1; a2B[n2][2] = bb0; a2B[n2][3] = bb1;
        }

        for (int nt = 0; nt < 64; nt++){
            float biac0 = b1s[nt * 8 + 2 * t];
            float biac1 = b1s[nt * 8 + 2 * t + 1];
            float cA0 = biac0, cA1 = biac1, cA2 = biac0, cA3 = biac1;
            float cB0 = biac0, cB1 = biac1, cB2 = biac0, cB3 = biac1;
            const uint2* w1p = (const uint2*)w1s + (nt * 4) * 32 + lane;
#pragma unroll
            for (int kc = 0; kc < 4; kc++){
                uint2 bb = w1p[kc * 32];
                mma_tf32(cA0, cA1, cA2, cA3,
                         azA[kc][0], azA[kc][1], azA[kc][2], azA[kc][3], bb.x, bb.y);
                mma_tf32(cB0, cB1, cB2, cB3,
                         azB[kc][0], azB[kc][1], azB[kc][2], azB[kc][3], bb.x, bb.y);
            }
            uint32_t xA0 = f2tf32(fmaxf(cA0, 0.0f));
            uint32_t xA1 = f2tf32(fmaxf(cA1, 0.0f));
            uint32_t xA2 = f2tf32(fmaxf(cA2, 0.0f));
            uint32_t xA3 = f2tf32(fmaxf(cA3, 0.0f));
            uint32_t xB0 = f2tf32(fmaxf(cB0, 0.0f));
            uint32_t xB1 = f2tf32(fmaxf(cB1, 0.0f));
            uint32_t xB2 = f2tf32(fmaxf(cB2, 0.0f));
            uint32_t xB3 = f2tf32(fmaxf(cB3, 0.0f));
            uint32_t aA0, aA1, aA2, aA3, aB0, aB1, aB2, aB3;
            dfrag_to_afrag(xA0, xA1, xA2, xA3, aA0, aA1, aA2, aA3, lane);
            dfrag_to_afrag(xB0, xB1, xB2, xB3, aB0, aB1, aB2, aB3, lane);

            const uint2* w2p = (const uint2*)w2s + nt * 32 + lane;
#pragma unroll
            for (int n2 = 0; n2 < 4; n2++){
                uint2 bb = w2p[n2 * 64 * 32];
                mma_tf32(a2A[n2][0], a2A[n2][1], a2A[n2][2], a2A[n2][3],
                         aA0, aA1, aA2, aA3, bb.x, bb.y);
                mma_tf32(a2B[n2][0], a2B[n2][1], a2B[n2][2], a2B[n2][3],
                         aB0, aB1, aB2, aB3, bb.x, bb.y);
            }
        }

#pragma unroll
        for (int sel = 0; sel < 2; sel++){
            float (*a2)[4] = sel ? a2B : a2A;
            const int r0 = (sel ? t1 : t0) * 16;
            float h0 = b3s[2 * t];
            float h1 = b3s[2 * t + 1];
            float h2 = h0, h3 = h1;
#pragma unroll
            for (int n2 = 0; n2 < 4; n2++){
                uint32_t x0 = f2tf32(fmaxf(a2[n2][0], 0.0f));
                uint32_t x1 = f2tf32(fmaxf(a2[n2][1], 0.0f));
                uint32_t x2 = f2tf32(fmaxf(a2[n2][2], 0.0f));
                uint32_t x3 = f2tf32(fmaxf(a2[n2][3], 0.0f));
                uint32_t aa0, aa1, aa2, aa3;
                dfrag_to_afrag(x0, x1, x2, x3, aa0, aa1, aa2, aa3, lane);
                uint2 bb = *((const uint2*)w3s + n2 * 32 + lane);
                mma_tf32(h0, h1, h2, h3, aa0, aa1, aa2, aa3, bb.x, bb.y);
            }
            const int rA = r0 + g;
            const int rB = rA + 8;
            outp[(size_t)rA * 7 + 2 * t] = h0;
            outp[(size_t)rB * 7 + 2 * t] = h2;
            if (t < 3){
                outp[(size_t)rA * 7 + 2 * t + 1] = h1;
                outp[(size_t)rB * 7 + 2 * t + 1] = h3;
            }
        }
    }
}

// ============================================================================
// launch
// ============================================================================
extern "C" void kernel_launch(void* const* d_in, const int* in_sizes, int n_in,
                              void* d_out, int out_size)
{
    const float* h    = (const float*)d_in[0];
    const float* Wmu  = (const float*)d_in[1];
    const float* bmu  = (const float*)d_in[2];
    const float* Wk   = (const float*)d_in[3];
    const float* bk   = (const float*)d_in[4];
    const float* W1   = (const float*)d_in[5];
    const float* b1   = (const float*)d_in[6];
    const float* W2   = (const float*)d_in[7];
    const float* b2   = (const float*)d_in[8];
    const float* W3   = (const float*)d_in[9];
    const float* b3   = (const float*)d_in[10];
    const int*   seed = (const int*)d_in[11];

    const int F = 512;
    const int B = in_sizes[0] / F;          // 131072
    float* outp = (float*)d_out;

    const int smemG = 8192 * 8 + (128 * 68 + 512) * 4 + 100 * 8;      // 102,752
    const int smemT = (16384 + 16384 + 256) * 4 + (512 + 32 + 8) * 4; // 134,304
    cudaFuncSetAttribute(k_gemmTCF, cudaFuncAttributeMaxDynamicSharedMemorySize, smemG);
    cudaFuncSetAttribute(k_mlp_tc,  cudaFuncAttributeMaxDynamicSharedMemorySize, smemT);

    k_setup<<<1, 64>>>(seed);
    k_packw<<<161, 256>>>(W1, W2, W3, Wmu);

    int n = B * 31;
    k_normals<<<(n + 255) / 256, 256>>>(n);

    k_gemmTCF<<<B / 128, 256, smemG>>>(h, bmu, Wk, bk, outp, B);

    k_mlp_tc<<<148, 256, smemT>>>(b1, b2, b3, outp, B, B / 16);
}

// round 16
// speedup vs baseline: 1.1677x; 1.1677x over previous
#include <cuda_runtime.h>
#include <cstdint>
#include <math.h>

// ============================================================================
// libdevice-matching transcendentals
// ============================================================================
#if defined(__USE_FAST_MATH__)
__device__ __forceinline__ float xlogf(float x){ return (float)log((double)x); }
__device__ __forceinline__ float xlog1pf(float x){ return (float)log1p((double)x); }
__device__ __forceinline__ float xexpf(float x){ return (float)exp((double)x); }
#else
__device__ __forceinline__ float xlogf(float x){ return logf(x); }
__device__ __forceinline__ float xlog1pf(float x){ return log1pf(x); }
__device__ __forceinline__ float xexpf(float x){ return expf(x); }
#endif

// ============================================================================
// Threefry-2x32 (exact JAX partitionable replication)
// ============================================================================
#define TF_C 0x1BD11BDAu

struct U2 { uint32_t a, b; };

__device__ __forceinline__ uint32_t rotl32(uint32_t x, int r){
    return __funnelshift_l(x, x, r);
}

__device__ __forceinline__ U2 threefry(uint32_t k0, uint32_t k1, uint32_t x0, uint32_t x1){
    uint32_t k2 = k0 ^ k1 ^ TF_C;
    x0 += k0; x1 += k1;
#define TFR(r) { x0 += x1; x1 = rotl32(x1, (r)); x1 ^= x0; }
    TFR(13) TFR(15) TFR(26) TFR(6)
    x0 += k1; x1 += k2 + 1u;
    TFR(17) TFR(29) TFR(16) TFR(24)
    x0 += k2; x1 += k0 + 2u;
    TFR(13) TFR(15) TFR(26) TFR(6)
    x0 += k0; x1 += k1 + 3u;
    TFR(17) TFR(29) TFR(16) TFR(24)
    x0 += k1; x1 += k2 + 4u;
    TFR(13) TFR(15) TFR(26) TFR(6)
    x0 += k2; x1 += k0 + 5u;
#undef TFR
    U2 r; r.a = x0; r.b = x1; return r;
}

__device__ __forceinline__ uint32_t tf_bits(uint32_t k0, uint32_t k1, uint32_t idx){
    U2 o = threefry(k0, k1, 0u, idx);
    return o.a ^ o.b;
}

__device__ __forceinline__ float u01(uint32_t bits){
    return __uint_as_float((bits >> 9) | 0x3f800000u) - 1.0f;
}

// XLA ErfInv32 (Giles polynomial)
__device__ __forceinline__ float erfinv_xla(float x){
    float w = -xlog1pf(-x * x);
    float p;
    if (w < 5.0f){
        w = w - 2.5f;
        p = 2.81022636e-08f;
        p = fmaf(p, w, 3.43273939e-07f);
        p = fmaf(p, w, -3.5233877e-06f);
        p = fmaf(p, w, -4.39150654e-06f);
        p = fmaf(p, w, 0.00021858087f);
        p = fmaf(p, w, -0.00125372503f);
        p = fmaf(p, w, -0.00417768164f);
        p = fmaf(p, w, 0.246640727f);
        p = fmaf(p, w, 1.50140941f);
    } else {
        w = sqrtf(w) - 3.0f;
        p = -0.000200214257f;
        p = fmaf(p, w, 0.000100950558f);
        p = fmaf(p, w, 0.00134934322f);
        p = fmaf(p, w, -0.00367342844f);
        p = fmaf(p, w, 0.00573950773f);
        p = fmaf(p, w, -0.0076224613f);
        p = fmaf(p, w, 0.00943887047f);
        p = fmaf(p, w, 1.00167406f);
        p = fmaf(p, w, 2.83297682f);
    }
    return p * x;
}

// ============================================================================
// tf32 helpers
// ============================================================================
__device__ __forceinline__ uint32_t f2tf32(float x){
    uint32_t r;
    asm("cvt.rna.tf32.f32 %0, %1;" : "=r"(r) : "f"(x));
    return r;
}

__device__ __forceinline__ void mma_tf32(
    float& c0, float& c1, float& c2, float& c3,
    uint32_t a0, uint32_t a1, uint32_t a2, uint32_t a3,
    uint32_t b0, uint32_t b1)
{
    asm volatile(
        "mma.sync.aligned.m16n8k8.row.col.f32.tf32.tf32.f32 "
        "{%0,%1,%2,%3},{%4,%5,%6,%7},{%8,%9},{%0,%1,%2,%3};"
        : "+f"(c0), "+f"(c1), "+f"(c2), "+f"(c3)
        : "r"(a0), "r"(a1), "r"(a2), "r"(a3), "r"(b0), "r"(b1));
}

// D fragment (m16n8) -> A fragment (m16k8) via intra-quad shuffles (validated)
__device__ __forceinline__ void dfrag_to_afrag(
    uint32_t x0, uint32_t x1, uint32_t x2, uint32_t x3,
    uint32_t& a0, uint32_t& a1, uint32_t& a2, uint32_t& a3, int lane)
{
    int t = lane & 3;
    int srcA = (lane & ~3) | (t >> 1);
    int srcB = srcA + 2;
    uint32_t s0 = __shfl_sync(0xffffffffu, x0, srcA);
    uint32_t s1 = __shfl_sync(0xffffffffu, x1, srcA);
    uint32_t s2 = __shfl_sync(0xffffffffu, x0, srcB);
    uint32_t s3 = __shfl_sync(0xffffffffu, x1, srcB);
    a0 = (t & 1) ? s1 : s0;
    a2 = (t & 1) ? s3 : s2;
    uint32_t u0 = __shfl_sync(0xffffffffu, x2, srcA);
    uint32_t u1 = __shfl_sync(0xffffffffu, x3, srcA);
    uint32_t u2 = __shfl_sync(0xffffffffu, x2, srcB);
    uint32_t u3 = __shfl_sync(0xffffffffu, x3, srcB);
    a1 = (t & 1) ? u1 : u0;
    a3 = (t & 1) ? u3 : u2;
}

// ============================================================================
// Device scratch
// ============================================================================
__device__ uint2 g_k1[64];
__device__ uint2 g_k2[64];
__device__ uint2 g_kv;
__device__ float g_norm[4194304];    // [B][32] raw normals (31 used)
__device__ uint32_t g_zf[4194304];   // z in tf32 A-fragment layout
__device__ uint32_t g_w1f[16384];    // W1 B-fragments (tf32 bits)
__device__ uint32_t g_w2f[16384];    // W2 B-fragments
__device__ uint32_t g_w3f[256];      // W3 B-fragments (col 7 zero)
__device__ uint2 g_wmuh[8192];       // Wmu B-fragments, hi part

// ============================================================================
// Kernel 1: RNG keys (partitionable semantics)
// ============================================================================
__global__ void k_setup(const int* __restrict__ seedp){
    int i = threadIdx.x;
    uint32_t s = (uint32_t)seedp[0];
    if (i < 50){
        U2 fk = threefry(0u, s, 0u, (uint32_t)i);
        U2 kw = threefry(fk.a, fk.b, 0u, 0u);
        U2 kr = threefry(fk.a, fk.b, 0u, 1u);
        g_k1[i] = make_uint2(kw.a, kw.b);
        g_k2[i] = make_uint2(kr.a, kr.b);
    } else if (i == 50){
        U2 kv = threefry(0u, s, 0u, 10000u);
        g_kv = make_uint2(kv.a, kv.b);
    }
}

// ============================================================================
// Kernel 1b: pack weights into tf32 B-fragments (W1/W2/W3 + Wmu hi)
// ============================================================================
__global__ void k_packw(const float* __restrict__ W1,
                        const float* __restrict__ W2,
                        const float* __restrict__ W3,
                        const float* __restrict__ Wmu){
    int j = blockIdx.x * 256 + threadIdx.x;
    if (j < 16384){
        int p = j & 1, lane = (j >> 1) & 31, kc = (j >> 6) & 3, nt = j >> 8;
        int g = lane >> 2, t = lane & 3;
        g_w1f[j] = f2tf32(W1[(nt * 8 + g) * 32 + kc * 8 + t + 4 * p]);
    } else if (j < 32768){
        int j2 = j - 16384;
        int p = j2 & 1, lane = (j2 >> 1) & 31, kc2 = (j2 >> 6) & 63, nt2 = j2 >> 12;
        int g = lane >> 2, t = lane & 3;
        g_w2f[j2] = f2tf32(W2[(nt2 * 8 + g) * 512 + kc2 * 8 + t + 4 * p]);
    } else if (j < 33024){
        int j3 = j - 32768;
        int p = j3 & 1, lane = (j3 >> 1) & 31, kc = (j3 >> 6) & 3;
        int g = lane >> 2, t = lane & 3;
        g_w3f[j3] = (g < 7) ? f2tf32(W3[g * 32 + kc * 8 + t + 4 * p]) : 0u;
    } else if (j < 41216){
        int jm = j - 33024;                 // 0..8191
        int lane = jm & 31, nt = (jm >> 5) & 3, kc = jm >> 7;   // kc 0..63
        int g = lane >> 2, t = lane & 3;
        float x0 = Wmu[(nt * 8 + g) * 512 + kc * 8 + t];
        float x1 = Wmu[(nt * 8 + g) * 512 + kc * 8 + t + 4];
        g_wmuh[jm] = make_uint2(f2tf32(x0), f2tf32(x1));
    }
}

// ============================================================================
// Kernel 2: normals — RNG index e = b*31+c, stored at stride 32 (proven)
// ============================================================================
__global__ void __launch_bounds__(256) k_normals(int n){
    int e = blockIdx.x * 256 + threadIdx.x;
    if (e >= n) return;
    uint2 kv = g_kv;
    uint32_t bits = tf_bits(kv.x, kv.y, (uint32_t)e);
    float f = u01(bits);
    const float lo = -0.99999994f;
    float u = fmaxf(lo, __fadd_rn(__fmul_rn(f, 2.0f), lo));
    int b = e / 31, c = e - b * 31;
    g_norm[b * 32 + c] = __fmul_rn(1.41421356f, erfinv_xla(u));
}

// ============================================================================
// Kernel 3: FUSED tensor-core encode GEMM + Wood + Householder + frag store.
// R16: register double-buffer with R14's COALESCED addressing
// (lin = tid + it*256, adjacent threads -> adjacent float4s).
// mu via 2-term split tf32; kappa exact fp32 chain. 128 rows/CTA, 2 CTAs/SM.
// ============================================================================
__global__ void __launch_bounds__(256, 2) k_gemmTCF(
    const float* __restrict__ h,
    const float* __restrict__ bmu,
    const float* __restrict__ Wk, const float* __restrict__ bk,
    float* __restrict__ outp, int B)
{
    extern __shared__ char smraw[];
    uint2* wh  = (uint2*)smraw;            // 8192 uint2 (64KB) Wmu hi frags
    float* hs  = (float*)(wh + 8192);      // [128][68] (34.8KB); reused as muS
    float* wks = hs + 128 * 68;            // [512]
    uint2* sk1 = (uint2*)(wks + 512);      // [50]
    uint2* sk2 = sk1 + 50;                 // [50]

    const int tid  = threadIdx.x;
    const int warp = tid >> 5;
    const int lane = tid & 31;
    const int g = lane >> 2;
    const int t = lane & 3;
    const int row0 = blockIdx.x * 128;

    // stage B fragments + Wk + RNG keys
    {
        const uint4* sh = (const uint4*)g_wmuh;
        uint4* dh = (uint4*)wh;
        for (int i = tid; i < 4096; i += 256) dh[i] = sh[i];
        for (int i = tid; i < 512; i += 256) wks[i] = Wk[i];
        if (tid < 50)       sk1[tid] = g_k1[tid];
        else if (tid < 100) sk2[tid - 50] = g_k2[tid - 50];
    }

    float acc[4][4];
#pragma unroll
    for (int nt = 0; nt < 4; nt++)
#pragma unroll
        for (int i = 0; i < 4; i++) acc[nt][i] = 0.0f;

    float ka = 0.0f;
    const float4* h4 = (const float4*)h;

    // coalesced per-it coordinates (same as R14's loader)
    const int pr = tid >> 4;               // base row for it-chunks (tid+it*256)>>4
    const int pq = tid & 15;               // float4 col within 16

    // prefetch chunk 0 (coalesced: adjacent threads -> adjacent float4s)
    float4 pre[8];
#pragma unroll
    for (int it = 0; it < 8; it++){
        int r = pr + it * 16;              // (tid + it*256)>>4 = pr + 16*it
        pre[it] = h4[(size_t)(row0 + r) * 128 + (size_t)pq];
    }

    for (int c = 0; c < 8; c++){                  // 8 chunks of 64 k
        __syncthreads();
        // commit prefetched chunk to smem (same indices)
#pragma unroll
        for (int it = 0; it < 8; it++){
            int r = pr + it * 16;
            *(float4*)&hs[r * 68 + pq * 4] = pre[it];
        }
        __syncthreads();

        // prefetch next chunk — LDGs overlap with mma/kappa compute below
        if (c < 7){
#pragma unroll
            for (int it = 0; it < 8; it++){
                int r = pr + it * 16;
                pre[it] = h4[(size_t)(row0 + r) * 128 + (size_t)((c + 1) * 16 + pq)];
            }
        }

        // --- mma over 8 k-groups (1 tile/warp = 16 rows) ---
#pragma unroll
        for (int kc = 0; kc < 8; kc++){
            const int rb = (warp * 16 + g) * 68 + kc * 8 + t;
            float a0f = hs[rb];
            float a1f = hs[rb + 8 * 68];
            float a2f = hs[rb + 4];
            float a3f = hs[rb + 8 * 68 + 4];
            uint32_t ah0 = f2tf32(a0f), ah1 = f2tf32(a1f);
            uint32_t ah2 = f2tf32(a2f), ah3 = f2tf32(a3f);
            uint32_t al0 = f2tf32(a0f - __uint_as_float(ah0));
            uint32_t al1 = f2tf32(a1f - __uint_as_float(ah1));
            uint32_t al2 = f2tf32(a2f - __uint_as_float(ah2));
            uint32_t al3 = f2tf32(a3f - __uint_as_float(ah3));
            const int kcg = c * 8 + kc;
#pragma unroll
            for (int nt = 0; nt < 4; nt++){
                uint2 bh = wh[(kcg * 4 + nt) * 32 + lane];
                mma_tf32(acc[nt][0], acc[nt][1], acc[nt][2], acc[nt][3],
                         al0, al1, al2, al3, bh.x, bh.y);
                mma_tf32(acc[nt][0], acc[nt][1], acc[nt][2], acc[nt][3],
                         ah0, ah1, ah2, ah3, bh.x, bh.y);
            }
        }

        // --- kappa: exact fp32 chain, k ascending, rows 0..127 (tid<128) ---
        if (tid < 128){
            const float4* hr = (const float4*)&hs[tid * 68];
#pragma unroll
            for (int q = 0; q < 16; q++){
                float4 v = hr[q];
                const int kb = c * 64 + q * 4;
                ka = fmaf(v.x, wks[kb],     ka);
                ka = fmaf(v.y, wks[kb + 1], ka);
                ka = fmaf(v.z, wks[kb + 2], ka);
                ka = fmaf(v.w, wks[kb + 3], ka);
            }
        }
    }

    // --- epilogue: bias + l2norm; write mu to gmem AND smem (muS) ---
    __syncthreads();                       // hs free -> reuse as muS [128][33]
    float* muS = hs;
    {
        float ssA = 0.0f, ssB = 0.0f;
#pragma unroll
        for (int nt = 0; nt < 4; nt++){
            float b0 = bmu[nt * 8 + 2 * t];
            float b1 = bmu[nt * 8 + 2 * t + 1];
            acc[nt][0] += b0; acc[nt][1] += b1;
            acc[nt][2] += b0; acc[nt][3] += b1;
            ssA = fmaf(acc[nt][0], acc[nt][0], ssA);
            ssA = fmaf(acc[nt][1], acc[nt][1], ssA);
            ssB = fmaf(acc[nt][2], acc[nt][2], ssB);
            ssB = fmaf(acc[nt][3], acc[nt][3], ssB);
        }
        ssA += __shfl_xor_sync(0xffffffffu, ssA, 1);
        ssA += __shfl_xor_sync(0xffffffffu, ssA, 2);
        ssB += __shfl_xor_sync(0xffffffffu, ssB, 1);
        ssB += __shfl_xor_sync(0xffffffffu, ssB, 2);
        float denA = fmaxf(sqrtf(ssA), 1e-12f);
        float denB = fmaxf(sqrtf(ssB), 1e-12f);

        const int lA = warp * 16 + g;      // local rows
        const int lB = lA + 8;
        const int rA = row0 + lA;
        const int rB = row0 + lB;
        const size_t muA = (size_t)B * 7 + (size_t)rA * 32;
        const size_t muB = (size_t)B * 7 + (size_t)rB * 32;
#pragma unroll
        for (int nt = 0; nt < 4; nt++){
            float mA0 = acc[nt][0] / denA;
            float mA1 = acc[nt][1] / denA;
            float mB0 = acc[nt][2] / denB;
            float mB1 = acc[nt][3] / denB;
            outp[muA + nt * 8 + 2 * t]     = mA0;
            outp[muA + nt * 8 + 2 * t + 1] = mA1;
            outp[muB + nt * 8 + 2 * t]     = mB0;
            outp[muB + nt * 8 + 2 * t + 1] = mB1;
            muS[lA * 33 + nt * 8 + 2 * t]     = mA0;
            muS[lA * 33 + nt * 8 + 2 * t + 1] = mA1;
            muS[lB * 33 + nt * 8 + 2 * t]     = mB0;
            muS[lB * 33 + nt * 8 + 2 * t + 1] = mB1;
        }
    }

    // --- kappa epilogue (exact fp32 ops as all passing rounds) ---
    float kappa = 0.0f;
    if (tid < 128){
        float x = __fadd_rn(ka, bk[0]);
        float sp = __fadd_rn(fmaxf(x, 0.0f), xlog1pf(xexpf(-fabsf(x))));
        kappa = __fadd_rn(sp, 1.0f);
        outp[(size_t)B * 39 + (row0 + tid)] = kappa;
    }
    __syncthreads();

    // --- fused z-prep: Wood + z_tilde + Householder + frag store (tid<128) ---
    if (tid < 128){
        const int row = row0 + tid;
        const uint32_t ub = (uint32_t)row;

        // Wood's rejection (exact f32 op order)
        float w = 0.0f;
        bool done = false;
        for (int i = 0; i < 50; i++){
            if (__all_sync(0xffffffffu, done)) break;
            if (!done){
                uint2 K1 = sk1[i];
                float u1 = u01(tf_bits(K1.x, K1.y, ub));
                float wc = __fsub_rn(__fmul_rn(2.0f, u1), 1.0f);
                float omw = fmaxf(__fsub_rn(1.0f, __fmul_rn(wc, wc)), 1e-38f);
                float logp = __fadd_rn(__fmul_rn(kappa, wc), __fmul_rn(14.5f, xlogf(omw)));
                uint2 K2 = sk2[i];
                float u2 = u01(tf_bits(K2.x, K2.y, ub));
                float logr = xlogf(__fadd_rn(u2, 1e-38f));
                if (__fadd_rn(logr, kappa) <= logp){ w = wc; done = true; }
            }
        }
        w = fminf(fmaxf(w, -1.0f), 1.0f);

        // z_tilde
        float z[32];
        {
            const float4* nv = (const float4*)&g_norm[(size_t)row * 32];
#pragma unroll
            for (int q = 0; q < 8; q++){
                float4 v = nv[q];
                z[q * 4 + 0] = v.x; z[q * 4 + 1] = v.y;
                z[q * 4 + 2] = v.z; z[q * 4 + 3] = v.w;
            }
            z[31] = 0.0f;
            float ssn = 0.0f;
#pragma unroll
            for (int c = 0; c < 31; c++) ssn = fmaf(z[c], z[c], ssn);
            float den = fmaxf(sqrtf(ssn), 1e-12f);
            float st  = sqrtf(fmaxf(__fsub_rn(1.0f, __fmul_rn(w, w)), 1e-38f));
            float sc  = st / den;
#pragma unroll
            for (int c = 0; c < 31; c++) z[c] *= sc;
            z[31] = w;
        }

        // Householder (mu from smem)
        {
            const float* mrow = &muS[tid * 33];
            float uh[32];
            float ssu = 0.0f;
#pragma unroll
            for (int q = 0; q < 8; q++){
                float m0 = mrow[q * 4 + 0];
                float m1 = mrow[q * 4 + 1];
                float m2 = mrow[q * 4 + 2];
                float m3 = mrow[q * 4 + 3];
                float t0 = ((q * 4 + 0) == 31 ? 1.0f : 0.0f) - m0;
                float t1 = ((q * 4 + 1) == 31 ? 1.0f : 0.0f) - m1;
                float t2 = ((q * 4 + 2) == 31 ? 1.0f : 0.0f) - m2;
                float t3 = ((q * 4 + 3) == 31 ? 1.0f : 0.0f) - m3;
                uh[q * 4 + 0] = t0; uh[q * 4 + 1] = t1;
                uh[q * 4 + 2] = t2; uh[q * 4 + 3] = t3;
                ssu = fmaf(t0, t0, ssu); ssu = fmaf(t1, t1, ssu);
                ssu = fmaf(t2, t2, ssu); ssu = fmaf(t3, t3, ssu);
            }
            float inv = 1.0f / fmaxf(sqrtf(ssu), 1e-12f);
            float dot = 0.0f;
#pragma unroll
            for (int j = 0; j < 32; j++){
                uh[j] *= inv;
                dot = fmaf(z[j], uh[j], dot);
            }
            float d2 = 2.0f * dot;
#pragma unroll
            for (int j = 0; j < 32; j++) z[j] = fmaf(-d2, uh[j], z[j]);
        }

        // frag store (validated layout)
        {
            const int tIdx = row >> 4;
            const int lrr  = row & 15;
            const int gg   = lrr & 7;
            const int hhp  = (lrr >> 3) & 1;
#pragma unroll
            for (int kc = 0; kc < 4; kc++){
#pragma unroll
                for (int tt = 0; tt < 4; tt++){
                    size_t base = ((size_t)(tIdx * 4 + kc) * 32 + (gg * 4 + tt)) * 4;
                    g_zf[base + hhp]     = f2tf32(z[kc * 8 + tt]);
                    g_zf[base + 2 + hhp] = f2tf32(z[kc * 8 + tt + 4]);
                }
            }
        }
    }
}

// ============================================================================
// Kernel 4: tensor-core MLP, 2 tiles per warp (proven R12-R15)
// ============================================================================
__global__ void __launch_bounds__(256) k_mlp_tc(
    const float* __restrict__ b1, const float* __restrict__ b2,
    const float* __restrict__ b3,
    float* __restrict__ outp, int B, int nTiles)
{
    extern __shared__ char smraw[];
    uint32_t* w1s = (uint32_t*)smraw;        // 16384
    uint32_t* w2s = w1s + 16384;             // 16384
    uint32_t* w3s = w2s + 16384;             // 256
    float* b1s = (float*)(w3s + 256);        // 512
    float* b2s = b1s + 512;                  // 32
    float* b3s = b2s + 32;                   // 8

    const int tid = threadIdx.x;
    {
        const uint4* s1 = (const uint4*)g_w1f;
        const uint4* s2 = (const uint4*)g_w2f;
        uint4* d1 = (uint4*)w1s;
        uint4* d2 = (uint4*)w2s;
        for (int i = tid; i < 4096; i += 256){ d1[i] = s1[i]; d2[i] = s2[i]; }
        if (tid < 64) ((uint4*)w3s)[tid] = ((const uint4*)g_w3f)[tid];
        for (int i = tid; i < 512; i += 256) b1s[i] = b1[i];
        if (tid < 32) b2s[tid] = b2[tid];
        if (tid < 8)  b3s[tid] = (tid < 7) ? b3[tid] : 0.0f;
    }
    __syncthreads();

    const int warp = tid >> 5;
    const int lane = tid & 31;
    const int g = lane >> 2;
    const int t = lane & 3;
    const int nPairs = nTiles >> 1;

    for (int tp = blockIdx.x * 8 + warp; tp < nPairs; tp += 148 * 8){
        const int t0 = 2 * tp, t1 = t0 + 1;

        uint32_t azA[4][4], azB[4][4];
        {
            const uint4* zpA = (const uint4*)&g_zf[(size_t)t0 * 512];
            const uint4* zpB = (const uint4*)&g_zf[(size_t)t1 * 512];
#pragma unroll
            for (int kc = 0; kc < 4; kc++){
                uint4 vA = zpA[kc * 32 + lane];
                azA[kc][0] = vA.x; azA[kc][1] = vA.y; azA[kc][2] = vA.z; azA[kc][3] = vA.w;
                uint4 vB = zpB[kc * 32 + lane];
                azB[kc][0] = vB.x; azB[kc][1] = vB.y; azB[kc][2] = vB.z; azB[kc][3] = vB.w;
            }
        }

        float a2A[4][4], a2B[4][4];
#pragma unroll
        for (int n2 = 0; n2 < 4; n2++){
            float bb0 = b2s[n2 * 8 + 2 * t];
            float bb1 = b2s[n2 * 8 + 2 * t + 1];
            a2A[n2][0] = bb0; a2A[n2][1] = bb1; a2A[n2][2] = bb0; a2A[n2][3] = bb1;
            a2B[n2][0] = bb0; a2B[n2][1] = bb1; a2B[n2][2] = bb0; a2B[n2][3] = bb1;
        }

        for (int nt = 0; nt < 64; nt++){
            float biac0 = b1s[nt * 8 + 2 * t];
            float biac1 = b1s[nt * 8 + 2 * t + 1];
            float cA0 = biac0, cA1 = biac1, cA2 = biac0, cA3 = biac1;
            float cB0 = biac0, cB1 = biac1, cB2 = biac0, cB3 = biac1;
            const uint2* w1p = (const uint2*)w1s + (nt * 4) * 32 + lane;
#pragma unroll
            for (int kc = 0; kc < 4; kc++){
                uint2 bb = w1p[kc * 32];
                mma_tf32(cA0, cA1, cA2, cA3,
                         azA[kc][0], azA[kc][1], azA[kc][2], azA[kc][3], bb.x, bb.y);
                mma_tf32(cB0, cB1, cB2, cB3,
                         azB[kc][0], azB[kc][1], azB[kc][2], azB[kc][3], bb.x, bb.y);
            }
            uint32_t xA0 = f2tf32(fmaxf(cA0, 0.0f));
            uint32_t xA1 = f2tf32(fmaxf(cA1, 0.0f));
            uint32_t xA2 = f2tf32(fmaxf(cA2, 0.0f));
            uint32_t xA3 = f2tf32(fmaxf(cA3, 0.0f));
            uint32_t xB0 = f2tf32(fmaxf(cB0, 0.0f));
            uint32_t xB1 = f2tf32(fmaxf(cB1, 0.0f));
            uint32_t xB2 = f2tf32(fmaxf(cB2, 0.0f));
            uint32_t xB3 = f2tf32(fmaxf(cB3, 0.0f));
            uint32_t aA0, aA1, aA2, aA3, aB0, aB1, aB2, aB3;
            dfrag_to_afrag(xA0, xA1, xA2, xA3, aA0, aA1, aA2, aA3, lane);
            dfrag_to_afrag(xB0, xB1, xB2, xB3, aB0, aB1, aB2, aB3, lane);

            const uint2* w2p = (const uint2*)w2s + nt * 32 + lane;
#pragma unroll
            for (int n2 = 0; n2 < 4; n2++){
                uint2 bb = w2p[n2 * 64 * 32];
                mma_tf32(a2A[n2][0], a2A[n2][1], a2A[n2][2], a2A[n2][3],
                         aA0, aA1, aA2, aA3, bb.x, bb.y);
                mma_tf32(a2B[n2][0], a2B[n2][1], a2B[n2][2], a2B[n2][3],
                         aB0, aB1, aB2, aB3, bb.x, bb.y);
            }
        }

#pragma unroll
        for (int sel = 0; sel < 2; sel++){
            float (*a2)[4] = sel ? a2B : a2A;
            const int r0 = (sel ? t1 : t0) * 16;
            float h0 = b3s[2 * t];
            float h1 = b3s[2 * t + 1];
            float h2 = h0, h3 = h1;
#pragma unroll
            for (int n2 = 0; n2 < 4; n2++){
                uint32_t x0 = f2tf32(fmaxf(a2[n2][0], 0.0f));
                uint32_t x1 = f2tf32(fmaxf(a2[n2][1], 0.0f));
                uint32_t x2 = f2tf32(fmaxf(a2[n2][2], 0.0f));
                uint32_t x3 = f2tf32(fmaxf(a2[n2][3], 0.0f));
                uint32_t aa0, aa1, aa2, aa3;
                dfrag_to_afrag(x0, x1, x2, x3, aa0, aa1, aa2, aa3, lane);
                uint2 bb = *((const uint2*)w3s + n2 * 32 + lane);
                mma_tf32(h0, h1, h2, h3, aa0, aa1, aa2, aa3, bb.x, bb.y);
            }
            const int rA = r0 + g;
            const int rB = rA + 8;
            outp[(size_t)rA * 7 + 2 * t] = h0;
            outp[(size_t)rB * 7 + 2 * t] = h2;
            if (t < 3){
                outp[(size_t)rA * 7 + 2 * t + 1] = h1;
                outp[(size_t)rB * 7 + 2 * t + 1] = h3;
            }
        }
    }
}

// ============================================================================
// launch
// ============================================================================
extern "C" void kernel_launch(void* const* d_in, const int* in_sizes, int n_in,
                              void* d_out, int out_size)
{
    const float* h    = (const float*)d_in[0];
    const float* Wmu  = (const float*)d_in[1];
    const float* bmu  = (const float*)d_in[2];
    const float* Wk   = (const float*)d_in[3];
    const float* bk   = (const float*)d_in[4];
    const float* W1   = (const float*)d_in[5];
    const float* b1   = (const float*)d_in[6];
    const float* W2   = (const float*)d_in[7];
    const float* b2   = (const float*)d_in[8];
    const float* W3   = (const float*)d_in[9];
    const float* b3   = (const float*)d_in[10];
    const int*   seed = (const int*)d_in[11];

    const int F = 512;
    const int B = in_sizes[0] / F;          // 131072
    float* outp = (float*)d_out;

    const int smemG = 8192 * 8 + (128 * 68 + 512) * 4 + 100 * 8;      // 102,752
    const int smemT = (16384 + 16384 + 256) * 4 + (512 + 32 + 8) * 4; // 134,304
    cudaFuncSetAttribute(k_gemmTCF, cudaFuncAttributeMaxDynamicSharedMemorySize, smemG);
    cudaFuncSetAttribute(k_mlp_tc,  cudaFuncAttributeMaxDynamicSharedMemorySize, smemT);

    k_setup<<<1, 64>>>(seed);
    k_packw<<<161, 256>>>(W1, W2, W3, Wmu);

    int n = B * 31;
    k_normals<<<(n + 255) / 256, 256>>>(n);

    k_gemmTCF<<<B / 128, 256, smemG>>>(h, bmu, Wk, bk, outp, B);

    k_mlp_tc<<<148, 256, smemT>>>(b1, b2, b3, outp, B, B / 16);
}